// round 15
// baseline (speedup 1.0000x reference)
#include <cuda_runtime.h>

#define BB 4
#define CC 16
#define HH 384
#define WW 384
#define NPIX (HH*WW)
#define IMG  (BB*NPIX)
#define WSN  (BB*CC*NPIX)

typedef unsigned long long u64;

// ---------------- device scratch ----------------
__device__ float2 g_ws[WSN];       // layout R: stored[32k+l] = natural[32k+brev5(l)]
__device__ float2 g_s [WSN];       // permuted smaps: g_s[row][32j+l] = s[row][12l+j]
__device__ float2 g_p [IMG];       // T layout: [32j+l] <-> natural 12l+j
__device__ float2 g_r [IMG];       // T layout
__device__ float2 g_Ap[IMG];       // T layout
__device__ float  g_part_rr [BB*HH];   // measured |r|^2 row partials
__device__ float  g_part_pap[BB*HH];
__device__ float  g_part_rap[BB*HH];
__device__ float  g_part_apap[BB*HH];
__device__ float  g_scal[2*BB];    // {alpha, beta} per batch (written by pass3 tail)
__device__ int    g_cnt [BB];      // pass3 completion counters (self-resetting)
__device__ volatile int g_flag[BB]; // release flag: it+1 once g_scal ready (reset by k_init)
__device__ float2 g_tw[384];
__device__ float  g_mask2[BB*WW*HH]; // [b][storedcol][32m+lane]

// ---------------- scalar complex helpers ----------------
__device__ __forceinline__ float2 cmul(float2 a, float2 b){
    return make_float2(fmaf(a.x,b.x,-a.y*b.y), fmaf(a.x,b.y, a.y*b.x));
}
__device__ __forceinline__ float2 cneg(float2 a){ return make_float2(-a.x, -a.y); }
__device__ __forceinline__ int brev5(int lane){ return (int)(__brev((unsigned)lane) >> 27); }

// ---------------- f32x2 packed helpers ----------------
__device__ __forceinline__ u64 pk2(float lo, float hi){
    u64 r; asm("mov.b64 %0, {%1, %2};" : "=l"(r) : "r"(__float_as_uint(lo)), "r"(__float_as_uint(hi))); return r;
}
__device__ __forceinline__ u64 bc2(float v){ return pk2(v, v); }
__device__ __forceinline__ void unpk2(u64 v, float& lo, float& hi){
    unsigned a, b; asm("mov.b64 {%0, %1}, %2;" : "=r"(a), "=r"(b) : "l"(v));
    lo = __uint_as_float(a); hi = __uint_as_float(b);
}
__device__ __forceinline__ u64 add2(u64 a, u64 b){ u64 r; asm("add.rn.f32x2 %0, %1, %2;" : "=l"(r) : "l"(a), "l"(b)); return r; }
__device__ __forceinline__ u64 mul2(u64 a, u64 b){ u64 r; asm("mul.rn.f32x2 %0, %1, %2;" : "=l"(r) : "l"(a), "l"(b)); return r; }
__device__ __forceinline__ u64 fma2(u64 a, u64 b, u64 c){ u64 r; asm("fma.rn.f32x2 %0, %1, %2, %3;" : "=l"(r) : "l"(a), "l"(b), "l"(c)); return r; }

struct C2 { u64 re, im; };
__device__ __forceinline__ C2 cadd2(C2 a, C2 b){ C2 r; r.re = add2(a.re,b.re); r.im = add2(a.im,b.im); return r; }
__device__ __forceinline__ C2 csub2(C2 a, C2 b, u64 m1){ C2 r; r.re = fma2(b.re,m1,a.re); r.im = fma2(b.im,m1,a.im); return r; }
__device__ __forceinline__ C2 cmulc2(C2 v, u64 pa, u64 pb, u64 pnb){
    C2 r;
    r.re = fma2(v.re, pa, mul2(v.im, pnb));
    r.im = fma2(v.im, pa, mul2(v.re, pb));
    return r;
}
__device__ __forceinline__ C2 cmulw2(C2 v, u64 wre, u64 wim, u64 wnim){
    C2 r;
    r.re = fma2(v.re, wre, mul2(v.im, wnim));
    r.im = fma2(v.re, wim, mul2(v.im, wre));
    return r;
}

// ---------------- init: tw + mask2 + permuted smaps + flag reset ----------------
__global__ void __launch_bounds__(384) k_init(const float* __restrict__ mask,
                                              const float* __restrict__ sre,
                                              const float* __restrict__ sim){
    int row = blockIdx.x;              // [0, B*C*H)
    int w = threadIdx.x;               // 0..383
    if (row == 0){
        float s, c;
        sincospif((float)w / 192.0f, &s, &c);
        g_tw[w] = make_float2(c, -s);
        if (w < BB){ g_flag[w] = 0; g_cnt[w] = 0; }
    }
    if (row < BB*WW){
        int b = row / WW, c = row % WW;          // c = stored column
        int m = w >> 5, lane = w & 31;
        int hk = 12*brev5(lane) + m;
        int wn = (c & ~31) | brev5(c & 31);
        g_mask2[row*HH + w] = mask[(b*HH + hk)*WW + wn];
    }
    int base = row * WW;
    g_s[base + 32*(w%12) + (w/12)] = make_float2(sre[base+w], sim[base+w]);
}

template<bool INV>
__device__ __forceinline__ float2 twbase(int idx){
    float2 u = g_tw[idx];
    if (INV) u.y = -u.y;
    return u;
}

__device__ __forceinline__ void makeT(float2 u, float2 T[4]){
    float2 u2 = cmul(u,u), u4 = cmul(u2,u2), u8 = cmul(u4,u4);
    float2 u12= cmul(u8,u4), u24 = cmul(u12,u12), u48 = cmul(u24,u24), u96 = cmul(u48,u48);
    T[0]=cneg(u12); T[1]=cneg(u24); T[2]=cneg(u48); T[3]=cneg(u96);
}

// ---------------- packed FFT machinery ----------------
template<bool INV>
__device__ __forceinline__ void dft12_2(C2 z[12], u64 m1){
    const float Cc = 0.86602540378443864676f;
    u64 pC = bc2(Cc), pnC = bc2(-Cc), p5 = bc2(0.5f), pn5 = bc2(-0.5f);
    const u64 bC  = INV ? pnC : pC;
    const u64 bnC = INV ? pC  : pnC;
    const u64 b5  = INV ? pn5 : p5;
    const u64 bn5 = INV ? p5  : pn5;
    C2 Y[12];
    #pragma unroll
    for (int r = 0; r < 3; r++){
        C2 x0=z[r], x1=z[r+3], x2=z[r+6], x3=z[r+9];
        C2 t0 = cadd2(x0,x2), t1 = csub2(x0,x2,m1);
        C2 t2 = cadd2(x1,x3), t3 = csub2(x1,x3,m1);
        C2 jt3;
        if (!INV){ jt3.re = t3.im; jt3.im = mul2(t3.re, m1); }
        else     { jt3.re = mul2(t3.im, m1); jt3.im = t3.re; }
        Y[4*r+0]=cadd2(t0,t2); Y[4*r+1]=cadd2(t1,jt3);
        Y[4*r+2]=csub2(t0,t2,m1); Y[4*r+3]=csub2(t1,jt3,m1);
    }
    z[0] = cadd2(Y[0], cadd2(Y[4], Y[8]));
    z[1] = cadd2(Y[1], cadd2(cmulc2(Y[5], pC, bn5, b5),  cmulc2(Y[9],  p5,  bnC, bC)));
    z[2] = cadd2(Y[2], cadd2(cmulc2(Y[6], p5, bnC, bC),  cmulc2(Y[10], pn5, bnC, bC)));
    {
        C2 t = csub2(Y[3], Y[11], m1); C2 i7;
        if (!INV){ i7.re = Y[7].im; i7.im = mul2(Y[7].re, m1); }
        else     { i7.re = mul2(Y[7].im, m1); i7.im = Y[7].re; }
        z[3] = cadd2(t, i7);
    }
    z[4] = cadd2(Y[0], cadd2(cmulc2(Y[4], pn5, bnC, bC), cmulc2(Y[8],  pn5, bC, bnC)));
    z[5] = cadd2(Y[1], cadd2(cmulc2(Y[5], pnC, bn5, b5), cmulc2(Y[9],  p5,  bC, bnC)));
    z[6] = cadd2(csub2(Y[2], Y[6], m1), Y[10]);
    z[7] = cadd2(Y[3], cadd2(cmulc2(Y[7], pnC, b5, bn5), cmulc2(Y[11], p5,  bnC, bC)));
    z[8] = cadd2(Y[0], cadd2(cmulc2(Y[4], pn5, bC, bnC), cmulc2(Y[8],  pn5, bnC, bC)));
    {
        C2 t = csub2(Y[1], Y[9], m1); C2 i5;
        if (!INV){ i5.re = mul2(Y[5].im, m1); i5.im = Y[5].re; }
        else     { i5.re = Y[5].im; i5.im = mul2(Y[5].re, m1); }
        z[9] = cadd2(t, i5);
    }
    z[10] = cadd2(Y[2], cadd2(cmulc2(Y[6], p5, bC, bnC),  cmulc2(Y[10], pn5, bC, bnC)));
    z[11] = cadd2(Y[3], cadd2(cmulc2(Y[7], pC, b5, bn5),  cmulc2(Y[11], p5,  bC, bnC)));
}

template<bool REV>
__device__ __forceinline__ void gs32g_2(C2 v[12], int lane, const float2 T[4], u64 m1){
    u64 p1 = bc2(1.f);
    #pragma unroll
    for (int st = 0; st < 5; st++){
        int hp = REV ? (1 << st) : (16 >> st);
        bool up = (lane & hp) != 0;
        u64 sp = up ? m1 : p1;
        if (st < 4){
            float2 tau = up ? T[st] : make_float2(1.f, 0.f);
            u64 tre = bc2(tau.x), tim = bc2(tau.y), tnim = bc2(-tau.y);
            #pragma unroll
            for (int m = 0; m < 12; m++){
                u64 ore = __shfl_xor_sync(0xffffffffu, v[m].re, hp);
                u64 oim = __shfl_xor_sync(0xffffffffu, v[m].im, hp);
                u64 wre = fma2(v[m].re, sp, ore);
                u64 wim = fma2(v[m].im, sp, oim);
                v[m].re = fma2(wre, tre, mul2(wim, tnim));
                v[m].im = fma2(wre, tim, mul2(wim, tre));
            }
        } else {
            #pragma unroll
            for (int m = 0; m < 12; m++){
                u64 ore = __shfl_xor_sync(0xffffffffu, v[m].re, hp);
                u64 oim = __shfl_xor_sync(0xffffffffu, v[m].im, hp);
                v[m].re = fma2(v[m].re, sp, ore);
                v[m].im = fma2(v[m].im, sp, oim);
            }
        }
    }
}

__device__ __forceinline__ void twmul11_2(C2 v[12], float2 w){
    float2 ps[12];
    ps[1]=w;
    ps[2]=cmul(w,w);      ps[3]=cmul(ps[2],w);   ps[4]=cmul(ps[2],ps[2]);
    ps[5]=cmul(ps[4],w);  ps[6]=cmul(ps[4],ps[2]); ps[7]=cmul(ps[4],ps[3]);
    ps[8]=cmul(ps[4],ps[4]); ps[9]=cmul(ps[8],w); ps[10]=cmul(ps[8],ps[2]); ps[11]=cmul(ps[8],ps[3]);
    #pragma unroll
    for (int k = 1; k < 12; k++){
        u64 wre = bc2(ps[k].x), wim = bc2(ps[k].y), wnim = bc2(-ps[k].y);
        v[k] = cmulw2(v[k], wre, wim, wnim);
    }
}

template<bool INV>
__device__ __forceinline__ void fftA2(C2 v[12], int lane, u64 m1){
    dft12_2<INV>(v, m1);
    float2 u = twbase<INV>(lane);
    twmul11_2(v, u);
    float2 T[4]; makeT(u, T);
    gs32g_2<false>(v, lane, T, m1);
}
template<bool INV>
__device__ __forceinline__ void fftArev2(C2 v[12], int lane, u64 m1){
    dft12_2<INV>(v, m1);
    float2 u = twbase<INV>(brev5(lane));
    twmul11_2(v, u);
    float2 T[4]; makeT(u, T);
    gs32g_2<true>(v, lane, T, m1);
}
template<bool INV>
__device__ __forceinline__ void fftB2(C2 v[12], int lane, u64 m1){
    float2 T[4]; makeT(twbase<INV>(lane), T);
    gs32g_2<false>(v, lane, T, m1);
    twmul11_2(v, twbase<INV>(brev5(lane)));
    dft12_2<INV>(v, m1);
}
template<bool INV>
__device__ __forceinline__ void fftBrev2(C2 v[12], int lane, u64 m1){
    float2 T[4]; makeT(twbase<INV>(brev5(lane)), T);
    gs32g_2<true>(v, lane, T, m1);
    twmul11_2(v, twbase<INV>(lane));
    dft12_2<INV>(v, m1);
}

// ---------------- reductions ----------------
__device__ __forceinline__ float block_reduce(float v, float* sred, int nwarp){
    int lane = threadIdx.x & 31, w = threadIdx.x >> 5;
    #pragma unroll
    for (int o = 16; o; o >>= 1) v += __shfl_down_sync(0xffffffffu, v, o);
    if (lane == 0) sred[w] = v;
    __syncthreads();
    v = 0.f;
    if (w == 0 && lane < nwarp) v = sred[lane];
    if (w == 0){
        #pragma unroll
        for (int o = 16; o; o >>= 1) v += __shfl_down_sync(0xffffffffu, v, o);
    }
    __syncthreads();
    return v;
}

__device__ __forceinline__ void block_reduce3(float a, float b, float c,
                                              float* s3, int nwarp, float out[3]){
    int lane = threadIdx.x & 31, w = threadIdx.x >> 5;
    #pragma unroll
    for (int o = 16; o; o >>= 1){
        a += __shfl_down_sync(0xffffffffu, a, o);
        b += __shfl_down_sync(0xffffffffu, b, o);
        c += __shfl_down_sync(0xffffffffu, c, o);
    }
    if (lane == 0){ s3[w*3+0] = a; s3[w*3+1] = b; s3[w*3+2] = c; }
    __syncthreads();
    a = b = c = 0.f;
    if (w == 0 && lane < nwarp){ a = s3[lane*3+0]; b = s3[lane*3+1]; c = s3[lane*3+2]; }
    if (w == 0){
        #pragma unroll
        for (int o = 16; o; o >>= 1){
            a += __shfl_down_sync(0xffffffffu, a, o);
            b += __shfl_down_sync(0xffffffffu, b, o);
            c += __shfl_down_sync(0xffffffffu, c, o);
        }
    }
    out[0] = a; out[1] = b; out[2] = c;
    __syncthreads();
}

// ---------------- pass1 (packed, coil-paired): ws(R) = FFT_W( s * p ) ----------------
__global__ void __launch_bounds__(128) k_pass1(){
    int wid = threadIdx.x >> 5, lane = threadIdx.x & 31;
    int wtask = blockIdx.x * 4 + wid;         // [0, B*H*8)
    int cp = wtask & 7;
    int bh = wtask >> 3;
    int b = bh / HH, h = bh % HH;
    int baseA = ((b*CC + 2*cp)*HH + h)*WW;
    int baseB = baseA + HH*WW;
    int pbase = (b*HH + h)*WW;
    u64 m1 = bc2(-1.f);
    C2 v[12];
    #pragma unroll
    for (int j = 0; j < 12; j++){
        int o = 32*j + lane;
        float2 sA = __ldcs(&g_s[baseA + o]);
        float2 sB = __ldcs(&g_s[baseB + o]);
        float2 p  = g_p[pbase + o];
        u64 pre = bc2(p.x), pim = bc2(p.y);
        u64 sre = pk2(sA.x, sB.x), sim = pk2(sA.y, sB.y);
        u64 nsim = mul2(sim, m1);
        v[j].re = fma2(pre, sre, mul2(pim, nsim));
        v[j].im = fma2(pre, sim, mul2(pim, sre));
    }
    fftB2<false>(v, lane, m1);
    #pragma unroll
    for (int m = 0; m < 12; m++){
        float r0, r1, i0, i1;
        unpk2(v[m].re, r0, r1); unpk2(v[m].im, i0, i1);
        g_ws[baseA + 32*m + lane] = make_float2(r0, i0);
        g_ws[baseB + 32*m + lane] = make_float2(r1, i1);
    }
}

// ---------------- pass2 (packed): 2 stored columns per warp; FFT_H -> mask -> IFFT_H ----------
__global__ void __launch_bounds__(128) k_pass2(){
    __shared__ float sR[384*9], sI[384*9];
    int tid = threadIdx.x;
    int blk = blockIdx.x;                     // [0, B*C*48)
    int w0 = (blk % 48) * 8;
    int bc = blk / 48; int b = bc / CC;
    int basebc = bc * NPIX;
    const float4* src = (const float4*)(g_ws + basebc);
    for (int idx = tid; idx < 384*4; idx += 128){
        int hr = idx >> 2, c2 = idx & 3;
        float4 val = src[hr*(WW/2) + (w0>>1) + c2];
        int c0 = c2*2;
        sR[hr*9 + c0  ] = val.x; sI[hr*9 + c0  ] = val.y;
        sR[hr*9 + c0+1] = val.z; sI[hr*9 + c0+1] = val.w;
    }
    __syncthreads();
    int wrp = tid >> 5, lane = tid & 31;      // warp owns stored cols w0+wrp, w0+wrp+4
    u64 m1 = bc2(-1.f);
    C2 v[12];
    #pragma unroll
    for (int j = 0; j < 12; j++){
        int h = lane + 32*j;
        v[j].re = pk2(sR[h*9+wrp], sR[h*9+wrp+4]);
        v[j].im = pk2(sI[h*9+wrp], sI[h*9+wrp+4]);
    }
    fftA2<false>(v, lane, m1);                // lane holds k-row kb+m
    int mb0 = (b*WW + w0 + wrp    ) * HH;
    int mb1 = (b*WW + w0 + wrp + 4) * HH;
    #pragma unroll
    for (int m = 0; m < 12; m++){
        u64 pm = pk2(g_mask2[mb0 + 32*m + lane], g_mask2[mb1 + 32*m + lane]);
        v[m].re = mul2(v[m].re, pm);
        v[m].im = mul2(v[m].im, pm);
    }
    fftBrev2<true>(v, lane, m1);              // output natural over H
    #pragma unroll
    for (int m = 0; m < 12; m++){
        int h = lane + 32*m;
        float r0, r1, i0, i1;
        unpk2(v[m].re, r0, r1); unpk2(v[m].im, i0, i1);
        sR[h*9+wrp] = r0; sR[h*9+wrp+4] = r1;
        sI[h*9+wrp] = i0; sI[h*9+wrp+4] = i1;
    }
    __syncthreads();
    float4* dst = (float4*)(g_ws + basebc);
    for (int idx = tid; idx < 384*4; idx += 128){
        int hr = idx >> 2, c2 = idx & 3;
        int c0 = c2*2;
        dst[hr*(WW/2) + (w0>>1) + c2] =
            make_float4(sR[hr*9+c0], sI[hr*9+c0], sR[hr*9+c0+1], sI[hr*9+c0+1]);
    }
}

// ---------------- pass3 + fused update: blocks [0,B*H) do Ap+partials (+tail alpha/beta);
// blocks [B*H, 2*B*H) spin on the flag then do the CG vector update ----------
__global__ void __launch_bounds__(128) k_pass3u(int it, const float* __restrict__ lam_p,
                                                float2* __restrict__ out){
    __shared__ float aR[4*384], aI[4*384];
    __shared__ float s3[12];
    __shared__ float sred[8];
    __shared__ int sIsLast;
    int t = threadIdx.x;
    int wrp = t >> 5, lane = t & 31;

    if (blockIdx.x >= BB*HH){
        // ---- update part ----
        int bh = blockIdx.x - BB*HH; int b = bh / HH;
        if (t == 0){
            while (g_flag[b] != it + 1) __nanosleep(64);
        }
        __syncthreads();
        __threadfence();
        float a  = g_scal[2*b];
        float be = g_scal[2*b+1];
        int last = (it == 9);
        if (!last){
            float rr = 0.f;
            #pragma unroll
            for (int q = 0; q < 3; q++){
                int i = bh*WW + t + 128*q;    // T index
                float2 p = g_p[i], ap = g_Ap[i];
                float2 x = out[i];
                x.x = fmaf(a, p.x, x.x);   x.y = fmaf(a, p.y, x.y);
                out[i] = x;
                float2 r = g_r[i];
                r.x = fmaf(-a, ap.x, r.x); r.y = fmaf(-a, ap.y, r.y);
                g_r[i] = r;
                g_p[i] = make_float2(fmaf(be, p.x, r.x), fmaf(be, p.y, r.y));
                rr += fmaf(r.x, r.x, r.y*r.y);
            }
            float tot = block_reduce(rr, sred, 4);
            if (t == 0) g_part_rr[bh] = tot;  // measured; consumed by next iter's tail
        } else {
            float2 xs[3];
            #pragma unroll
            for (int q = 0; q < 3; q++){
                int i = bh*WW + t + 128*q;
                float2 p = g_p[i];
                float2 x = out[i];
                xs[q].x = fmaf(a, p.x, x.x); xs[q].y = fmaf(a, p.y, x.y);
            }
            __syncthreads();
            #pragma unroll
            for (int q = 0; q < 3; q++){
                int tt = t + 128*q;
                int n = 12*(tt & 31) + (tt >> 5);
                out[bh*WW + n] = xs[q];
            }
        }
        return;
    }

    // ---- pass3 part ----
    int bh = blockIdx.x;                      // [0, B*H)
    int b = bh / HH, h = bh % HH;
    u64 m1 = bc2(-1.f);
    C2 acc[12];
    #pragma unroll
    for (int m = 0; m < 12; m++){ acc[m].re = 0ULL; acc[m].im = 0ULL; }
    int base0 = (b*CC*HH + h)*WW;
    #pragma unroll 1
    for (int k = 0; k < 2; k++){
        int cA = wrp + 8*k, cB = cA + 4;
        int baseA = base0 + cA*HH*WW;
        int baseB = base0 + cB*HH*WW;
        C2 v[12];
        #pragma unroll
        for (int j = 0; j < 12; j++){
            float2 wA = __ldcs(&g_ws[baseA + 32*j + lane]);
            float2 wB = __ldcs(&g_ws[baseB + 32*j + lane]);
            v[j].re = pk2(wA.x, wB.x);
            v[j].im = pk2(wA.y, wB.y);
        }
        fftArev2<true>(v, lane, m1);          // lane holds Xinv[12*lane + m]
        #pragma unroll
        for (int m = 0; m < 12; m++){
            float2 sA = __ldcs(&g_s[baseA + 32*m + lane]);
            float2 sB = __ldcs(&g_s[baseB + 32*m + lane]);
            u64 sre = pk2(sA.x, sB.x), sim = pk2(sA.y, sB.y);
            acc[m].re = fma2(sim, v[m].im, fma2(sre, v[m].re, acc[m].re));
            acc[m].im = fma2(mul2(sim, m1), v[m].re, fma2(sre, v[m].im, acc[m].im));
        }
    }
    #pragma unroll
    for (int m = 0; m < 12; m++){
        float r0, r1, i0, i1;
        unpk2(acc[m].re, r0, r1); unpk2(acc[m].im, i0, i1);
        aR[wrp*384 + 32*m + lane] = r0 + r1;
        aI[wrp*384 + 32*m + lane] = i0 + i1;
    }
    __syncthreads();
    float lam = *lam_p;
    const float sc = 1.0f / (384.0f * 384.0f);
    float pap = 0.f, rap = 0.f, apap = 0.f;
    #pragma unroll
    for (int q = 0; q < 3; q++){
        int e = t + 128*q;                    // T index
        float ar = aR[e] + aR[384+e] + aR[768+e] + aR[1152+e];
        float ai = aI[e] + aI[384+e] + aI[768+e] + aI[1152+e];
        int idx = bh*WW + e;
        float2 pv = g_p[idx];
        float2 rv = g_r[idx];
        float2 ap = make_float2(fmaf(lam, pv.x, ar*sc), fmaf(lam, pv.y, ai*sc));
        g_Ap[idx] = ap;
        pap  += pv.x*ap.x + pv.y*ap.y;
        rap  += rv.x*ap.x + rv.y*ap.y;
        apap += ap.x*ap.x + ap.y*ap.y;
    }
    float out3[3];
    block_reduce3(pap, rap, apap, s3, 4, out3);
    if (t == 0){
        g_part_pap[bh] = out3[0]; g_part_rap[bh] = out3[1]; g_part_apap[bh] = out3[2];
        __threadfence();
        int old = atomicAdd(&g_cnt[b], 1);
        sIsLast = (old == HH - 1);
    }
    __syncthreads();
    if (sIsLast){
        __threadfence();
        float a1 = 0.f, a2 = 0.f, a3 = 0.f, rr = 0.f;
        #pragma unroll
        for (int q = 0; q < 3; q++){
            int e = b*HH + t + 128*q;
            a1 += g_part_pap[e]; a2 += g_part_rap[e]; a3 += g_part_apap[e];
            rr += g_part_rr[e];
        }
        float tot[3];
        block_reduce3(a1, a2, a3, s3, 4, tot);
        float rtr = block_reduce(rr, sred, 4);
        if (t == 0){
            g_cnt[b] = 0;
            float a = rtr / tot[0];
            float rtrN = fmaf(a*a, tot[2], fmaf(-2.f*a, tot[1], rtr));
            g_scal[2*b] = a; g_scal[2*b+1] = rtrN / rtr;
            __threadfence();
            g_flag[b] = it + 1;               // release
        }
    }
}

// ---------------- rhs pass 1 (packed): ws(natural) = IFFT_H( y * mask ) ----------------
__global__ void __launch_bounds__(128) k_rhs1(const float* __restrict__ yre,
                                              const float* __restrict__ yim,
                                              const float* __restrict__ mask){
    __shared__ float sR[384*9], sI[384*9];
    int tid = threadIdx.x;
    int blk = blockIdx.x;
    int w0 = (blk % 48) * 8;
    int bc = blk / 48; int b = bc / CC;
    int basebc = bc * NPIX;
    for (int idx = tid; idx < 384*8; idx += 128){
        int h = idx >> 3, cl = idx & 7;
        int g = basebc + h*WW + w0 + cl;
        float mv = mask[(b*HH + h)*WW + w0 + cl];
        sR[h*9+cl] = __ldcs(yre+g)*mv; sI[h*9+cl] = __ldcs(yim+g)*mv;
    }
    __syncthreads();
    int wrp = tid >> 5, lane = tid & 31;      // warp owns cols w0+wrp, w0+wrp+4
    u64 m1 = bc2(-1.f);
    C2 v[12];
    #pragma unroll
    for (int j = 0; j < 12; j++){
        int h = lane + 32*j;
        v[j].re = pk2(sR[h*9+wrp], sR[h*9+wrp+4]);
        v[j].im = pk2(sI[h*9+wrp], sI[h*9+wrp+4]);
    }
    fftA2<true>(v, lane, m1);                 // lane holds rows kb+m
    int kb = 12 * brev5(lane);
    __syncthreads();
    #pragma unroll
    for (int m = 0; m < 12; m++){
        float r0, r1, i0, i1;
        unpk2(v[m].re, r0, r1); unpk2(v[m].im, i0, i1);
        sR[(kb+m)*9+wrp] = r0; sR[(kb+m)*9+wrp+4] = r1;
        sI[(kb+m)*9+wrp] = i0; sI[(kb+m)*9+wrp+4] = i1;
    }
    __syncthreads();
    for (int idx = tid; idx < 384*8; idx += 128){
        int h = idx >> 3, cl = idx & 7;
        g_ws[basebc + h*WW + w0 + cl] = make_float2(sR[h*9+cl], sI[h*9+cl]);
    }
}

// ---------------- rhs pass 2 (packed): writes r,p in T layout; out = 0 ----------
__global__ void __launch_bounds__(128) k_rhs2(const float* __restrict__ xre,
                                              const float* __restrict__ xim,
                                              const float* __restrict__ lam_p,
                                              float2* __restrict__ out){
    __shared__ float aR[4*384], aI[4*384];
    __shared__ float sred[8];
    int wrp = threadIdx.x >> 5, lane = threadIdx.x & 31;
    int bh = blockIdx.x;
    int b = bh / HH, h = bh % HH;
    int kb = 12 * brev5(lane);
    int rb5 = brev5(lane);
    u64 m1 = bc2(-1.f);
    C2 acc[12];
    #pragma unroll
    for (int m = 0; m < 12; m++){ acc[m].re = 0ULL; acc[m].im = 0ULL; }
    int base0 = (b*CC*HH + h)*WW;
    #pragma unroll 1
    for (int k = 0; k < 2; k++){
        int cA = wrp + 8*k, cB = cA + 4;
        int baseA = base0 + cA*HH*WW;
        int baseB = base0 + cB*HH*WW;
        C2 v[12];
        #pragma unroll
        for (int j = 0; j < 12; j++){
            float2 wA = g_ws[baseA + lane + 32*j];
            float2 wB = g_ws[baseB + lane + 32*j];
            v[j].re = pk2(wA.x, wB.x);
            v[j].im = pk2(wA.y, wB.y);
        }
        fftA2<true>(v, lane, m1);             // lane holds natural kb+m
        #pragma unroll
        for (int m = 0; m < 12; m++){
            float2 sA = __ldcs(&g_s[baseA + 32*m + rb5]);
            float2 sB = __ldcs(&g_s[baseB + 32*m + rb5]);
            u64 sre = pk2(sA.x, sB.x), sim = pk2(sA.y, sB.y);
            acc[m].re = fma2(sim, v[m].im, fma2(sre, v[m].re, acc[m].re));
            acc[m].im = fma2(mul2(sim, m1), v[m].re, fma2(sre, v[m].im, acc[m].im));
        }
    }
    #pragma unroll
    for (int m = 0; m < 12; m++){
        float r0, r1, i0, i1;
        unpk2(acc[m].re, r0, r1); unpk2(acc[m].im, i0, i1);
        aR[wrp*384 + kb+m] = r0 + r1;
        aI[wrp*384 + kb+m] = i0 + i1;
    }
    __syncthreads();
    float lam = *lam_p;
    const float sc = 1.0f / 384.0f;   // ortho ifft2 total = unnormalized-inverse / 384
    float rr = 0.f;
    int t = threadIdx.x;
    #pragma unroll
    for (int q = 0; q < 3; q++){
        int e = t + 128*q;                    // natural index
        float ar = aR[e] + aR[384+e] + aR[768+e] + aR[1152+e];
        float ai = aI[e] + aI[384+e] + aI[768+e] + aI[1152+e];
        float2 rhs = make_float2(fmaf(lam, xre[bh*WW+e], ar*sc), fmaf(lam, xim[bh*WW+e], ai*sc));
        int ti = 32*(e%12) + e/12;            // T index
        g_r[bh*WW + ti] = rhs; g_p[bh*WW + ti] = rhs;
        out[bh*WW + e] = make_float2(0.f, 0.f);
        rr += rhs.x*rhs.x + rhs.y*rhs.y;
    }
    float tot = block_reduce(rr, sred, 4);
    if (t == 0) g_part_rr[bh] = tot;
}

// ---------------- launch ----------------
extern "C" void kernel_launch(void* const* d_in, const int* in_sizes, int n_in,
                              void* d_out, int out_size){
    (void)in_sizes; (void)n_in; (void)out_size;
    const float* lam  = (const float*)d_in[0];
    const float* xre  = (const float*)d_in[1];
    const float* xim  = (const float*)d_in[2];
    const float* yre  = (const float*)d_in[3];
    const float* yim  = (const float*)d_in[4];
    const float* sre  = (const float*)d_in[5];
    const float* sim  = (const float*)d_in[6];
    const float* mask = (const float*)d_in[7];
    float2* out = (float2*)d_out;

    k_init<<<BB*CC*HH, 384>>>(mask, sre, sim);
    k_rhs1<<<BB*CC*48, 128>>>(yre, yim, mask);
    k_rhs2<<<BB*HH, 128>>>(xre, xim, lam, out);

    for (int it = 0; it < 10; it++){
        k_pass1<<<BB*HH*8/4, 128>>>();
        k_pass2<<<BB*CC*48, 128>>>();
        k_pass3u<<<2*BB*HH, 128>>>(it, lam, out);
    }
}

// round 16
// speedup vs baseline: 1.0384x; 1.0384x over previous
#include <cuda_runtime.h>

#define BB 4
#define CC 16
#define HH 384
#define WW 384
#define NPIX (HH*WW)
#define IMG  (BB*NPIX)
#define WSN  (BB*CC*NPIX)

typedef unsigned long long u64;

// ---------------- device scratch ----------------
__device__ float2 g_ws[WSN];       // layout R: stored[32k+l] = natural[32k+brev5(l)]
__device__ float2 g_s [WSN];       // permuted smaps: g_s[row][32j+l] = s[row][12l+j]
__device__ float2 g_p [IMG];       // T layout: [32j+l] <-> natural 12l+j
__device__ float2 g_r [IMG];       // T layout
__device__ float2 g_Ap[IMG];       // T layout
__device__ float  g_part_rr [BB*HH];   // measured |r|^2 row partials
__device__ float  g_part_pap[BB*HH];
__device__ float  g_part_rap[BB*HH];
__device__ float  g_part_apap[BB*HH];
__device__ float  g_scal[2*BB];    // {alpha, beta} per batch (written by pass3 tail)
__device__ int    g_cnt [BB];      // pass3 completion counters (self-resetting)
__device__ float2 g_tw[384];
__device__ float  g_mask2[BB*WW*HH]; // [b][storedcol][32m+lane]

// ---------------- scalar complex helpers ----------------
__device__ __forceinline__ float2 cmul(float2 a, float2 b){
    return make_float2(fmaf(a.x,b.x,-a.y*b.y), fmaf(a.x,b.y, a.y*b.x));
}
__device__ __forceinline__ float2 cneg(float2 a){ return make_float2(-a.x, -a.y); }
__device__ __forceinline__ int brev5(int lane){ return (int)(__brev((unsigned)lane) >> 27); }

// ---------------- f32x2 packed helpers ----------------
__device__ __forceinline__ u64 pk2(float lo, float hi){
    u64 r; asm("mov.b64 %0, {%1, %2};" : "=l"(r) : "r"(__float_as_uint(lo)), "r"(__float_as_uint(hi))); return r;
}
__device__ __forceinline__ u64 bc2(float v){ return pk2(v, v); }
__device__ __forceinline__ void unpk2(u64 v, float& lo, float& hi){
    unsigned a, b; asm("mov.b64 {%0, %1}, %2;" : "=r"(a), "=r"(b) : "l"(v));
    lo = __uint_as_float(a); hi = __uint_as_float(b);
}
__device__ __forceinline__ u64 add2(u64 a, u64 b){ u64 r; asm("add.rn.f32x2 %0, %1, %2;" : "=l"(r) : "l"(a), "l"(b)); return r; }
__device__ __forceinline__ u64 mul2(u64 a, u64 b){ u64 r; asm("mul.rn.f32x2 %0, %1, %2;" : "=l"(r) : "l"(a), "l"(b)); return r; }
__device__ __forceinline__ u64 fma2(u64 a, u64 b, u64 c){ u64 r; asm("fma.rn.f32x2 %0, %1, %2, %3;" : "=l"(r) : "l"(a), "l"(b), "l"(c)); return r; }

struct C2 { u64 re, im; };
__device__ __forceinline__ C2 cadd2(C2 a, C2 b){ C2 r; r.re = add2(a.re,b.re); r.im = add2(a.im,b.im); return r; }
__device__ __forceinline__ C2 csub2(C2 a, C2 b, u64 m1){ C2 r; r.re = fma2(b.re,m1,a.re); r.im = fma2(b.im,m1,a.im); return r; }
__device__ __forceinline__ C2 cmulc2(C2 v, u64 pa, u64 pb, u64 pnb){
    C2 r;
    r.re = fma2(v.re, pa, mul2(v.im, pnb));
    r.im = fma2(v.im, pa, mul2(v.re, pb));
    return r;
}
__device__ __forceinline__ C2 cmulw2(C2 v, u64 wre, u64 wim, u64 wnim){
    C2 r;
    r.re = fma2(v.re, wre, mul2(v.im, wnim));
    r.im = fma2(v.re, wim, mul2(v.im, wre));
    return r;
}

// ---------------- init: tw + mask2 + permuted smaps ----------------
__global__ void __launch_bounds__(384) k_init(const float* __restrict__ mask,
                                              const float* __restrict__ sre,
                                              const float* __restrict__ sim){
    int row = blockIdx.x;              // [0, B*C*H)
    int w = threadIdx.x;               // 0..383
    if (row == 0){
        float s, c;
        sincospif((float)w / 192.0f, &s, &c);
        g_tw[w] = make_float2(c, -s);
    }
    if (row < BB*WW){
        int b = row / WW, c = row % WW;          // c = stored column
        int m = w >> 5, lane = w & 31;
        int hk = 12*brev5(lane) + m;
        int wn = (c & ~31) | brev5(c & 31);
        g_mask2[row*HH + w] = mask[(b*HH + hk)*WW + wn];
    }
    int base = row * WW;
    g_s[base + 32*(w%12) + (w/12)] = make_float2(sre[base+w], sim[base+w]);
}

template<bool INV>
__device__ __forceinline__ float2 twbase(int idx){
    float2 u = g_tw[idx];
    if (INV) u.y = -u.y;
    return u;
}

__device__ __forceinline__ void makeT(float2 u, float2 T[4]){
    float2 u2 = cmul(u,u), u4 = cmul(u2,u2), u8 = cmul(u4,u4);
    float2 u12= cmul(u8,u4), u24 = cmul(u12,u12), u48 = cmul(u24,u24), u96 = cmul(u48,u48);
    T[0]=cneg(u12); T[1]=cneg(u24); T[2]=cneg(u48); T[3]=cneg(u96);
}

// ---------------- packed FFT machinery ----------------
template<bool INV>
__device__ __forceinline__ void dft12_2(C2 z[12], u64 m1){
    const float Cc = 0.86602540378443864676f;
    u64 pC = bc2(Cc), pnC = bc2(-Cc), p5 = bc2(0.5f), pn5 = bc2(-0.5f);
    const u64 bC  = INV ? pnC : pC;
    const u64 bnC = INV ? pC  : pnC;
    const u64 b5  = INV ? pn5 : p5;
    const u64 bn5 = INV ? p5  : pn5;
    C2 Y[12];
    #pragma unroll
    for (int r = 0; r < 3; r++){
        C2 x0=z[r], x1=z[r+3], x2=z[r+6], x3=z[r+9];
        C2 t0 = cadd2(x0,x2), t1 = csub2(x0,x2,m1);
        C2 t2 = cadd2(x1,x3), t3 = csub2(x1,x3,m1);
        C2 jt3;
        if (!INV){ jt3.re = t3.im; jt3.im = mul2(t3.re, m1); }
        else     { jt3.re = mul2(t3.im, m1); jt3.im = t3.re; }
        Y[4*r+0]=cadd2(t0,t2); Y[4*r+1]=cadd2(t1,jt3);
        Y[4*r+2]=csub2(t0,t2,m1); Y[4*r+3]=csub2(t1,jt3,m1);
    }
    z[0] = cadd2(Y[0], cadd2(Y[4], Y[8]));
    z[1] = cadd2(Y[1], cadd2(cmulc2(Y[5], pC, bn5, b5),  cmulc2(Y[9],  p5,  bnC, bC)));
    z[2] = cadd2(Y[2], cadd2(cmulc2(Y[6], p5, bnC, bC),  cmulc2(Y[10], pn5, bnC, bC)));
    {
        C2 t = csub2(Y[3], Y[11], m1); C2 i7;
        if (!INV){ i7.re = Y[7].im; i7.im = mul2(Y[7].re, m1); }
        else     { i7.re = mul2(Y[7].im, m1); i7.im = Y[7].re; }
        z[3] = cadd2(t, i7);
    }
    z[4] = cadd2(Y[0], cadd2(cmulc2(Y[4], pn5, bnC, bC), cmulc2(Y[8],  pn5, bC, bnC)));
    z[5] = cadd2(Y[1], cadd2(cmulc2(Y[5], pnC, bn5, b5), cmulc2(Y[9],  p5,  bC, bnC)));
    z[6] = cadd2(csub2(Y[2], Y[6], m1), Y[10]);
    z[7] = cadd2(Y[3], cadd2(cmulc2(Y[7], pnC, b5, bn5), cmulc2(Y[11], p5,  bnC, bC)));
    z[8] = cadd2(Y[0], cadd2(cmulc2(Y[4], pn5, bC, bnC), cmulc2(Y[8],  pn5, bnC, bC)));
    {
        C2 t = csub2(Y[1], Y[9], m1); C2 i5;
        if (!INV){ i5.re = mul2(Y[5].im, m1); i5.im = Y[5].re; }
        else     { i5.re = Y[5].im; i5.im = mul2(Y[5].re, m1); }
        z[9] = cadd2(t, i5);
    }
    z[10] = cadd2(Y[2], cadd2(cmulc2(Y[6], p5, bC, bnC),  cmulc2(Y[10], pn5, bC, bnC)));
    z[11] = cadd2(Y[3], cadd2(cmulc2(Y[7], pC, b5, bn5),  cmulc2(Y[11], p5,  bC, bnC)));
}

template<bool REV>
__device__ __forceinline__ void gs32g_2(C2 v[12], int lane, const float2 T[4], u64 m1){
    u64 p1 = bc2(1.f);
    #pragma unroll
    for (int st = 0; st < 5; st++){
        int hp = REV ? (1 << st) : (16 >> st);
        bool up = (lane & hp) != 0;
        u64 sp = up ? m1 : p1;
        if (st < 4){
            float2 tau = up ? T[st] : make_float2(1.f, 0.f);
            u64 tre = bc2(tau.x), tim = bc2(tau.y), tnim = bc2(-tau.y);
            #pragma unroll
            for (int m = 0; m < 12; m++){
                u64 ore = __shfl_xor_sync(0xffffffffu, v[m].re, hp);
                u64 oim = __shfl_xor_sync(0xffffffffu, v[m].im, hp);
                u64 wre = fma2(v[m].re, sp, ore);
                u64 wim = fma2(v[m].im, sp, oim);
                v[m].re = fma2(wre, tre, mul2(wim, tnim));
                v[m].im = fma2(wre, tim, mul2(wim, tre));
            }
        } else {
            #pragma unroll
            for (int m = 0; m < 12; m++){
                u64 ore = __shfl_xor_sync(0xffffffffu, v[m].re, hp);
                u64 oim = __shfl_xor_sync(0xffffffffu, v[m].im, hp);
                v[m].re = fma2(v[m].re, sp, ore);
                v[m].im = fma2(v[m].im, sp, oim);
            }
        }
    }
}

__device__ __forceinline__ void twmul11_2(C2 v[12], float2 w){
    float2 ps[12];
    ps[1]=w;
    ps[2]=cmul(w,w);      ps[3]=cmul(ps[2],w);   ps[4]=cmul(ps[2],ps[2]);
    ps[5]=cmul(ps[4],w);  ps[6]=cmul(ps[4],ps[2]); ps[7]=cmul(ps[4],ps[3]);
    ps[8]=cmul(ps[4],ps[4]); ps[9]=cmul(ps[8],w); ps[10]=cmul(ps[8],ps[2]); ps[11]=cmul(ps[8],ps[3]);
    #pragma unroll
    for (int k = 1; k < 12; k++){
        u64 wre = bc2(ps[k].x), wim = bc2(ps[k].y), wnim = bc2(-ps[k].y);
        v[k] = cmulw2(v[k], wre, wim, wnim);
    }
}

template<bool INV>
__device__ __forceinline__ void fftA2(C2 v[12], int lane, u64 m1){
    dft12_2<INV>(v, m1);
    float2 u = twbase<INV>(lane);
    twmul11_2(v, u);
    float2 T[4]; makeT(u, T);
    gs32g_2<false>(v, lane, T, m1);
}
template<bool INV>
__device__ __forceinline__ void fftArev2(C2 v[12], int lane, u64 m1){
    dft12_2<INV>(v, m1);
    float2 u = twbase<INV>(brev5(lane));
    twmul11_2(v, u);
    float2 T[4]; makeT(u, T);
    gs32g_2<true>(v, lane, T, m1);
}
template<bool INV>
__device__ __forceinline__ void fftB2(C2 v[12], int lane, u64 m1){
    float2 T[4]; makeT(twbase<INV>(lane), T);
    gs32g_2<false>(v, lane, T, m1);
    twmul11_2(v, twbase<INV>(brev5(lane)));
    dft12_2<INV>(v, m1);
}
template<bool INV>
__device__ __forceinline__ void fftBrev2(C2 v[12], int lane, u64 m1){
    float2 T[4]; makeT(twbase<INV>(brev5(lane)), T);
    gs32g_2<true>(v, lane, T, m1);
    twmul11_2(v, twbase<INV>(lane));
    dft12_2<INV>(v, m1);
}

// ---------------- reductions ----------------
__device__ __forceinline__ float block_reduce(float v, float* sred, int nwarp){
    int lane = threadIdx.x & 31, w = threadIdx.x >> 5;
    #pragma unroll
    for (int o = 16; o; o >>= 1) v += __shfl_down_sync(0xffffffffu, v, o);
    if (lane == 0) sred[w] = v;
    __syncthreads();
    v = 0.f;
    if (w == 0 && lane < nwarp) v = sred[lane];
    if (w == 0){
        #pragma unroll
        for (int o = 16; o; o >>= 1) v += __shfl_down_sync(0xffffffffu, v, o);
    }
    __syncthreads();
    return v;
}

__device__ __forceinline__ void block_reduce3(float a, float b, float c,
                                              float* s3, int nwarp, float out[3]){
    int lane = threadIdx.x & 31, w = threadIdx.x >> 5;
    #pragma unroll
    for (int o = 16; o; o >>= 1){
        a += __shfl_down_sync(0xffffffffu, a, o);
        b += __shfl_down_sync(0xffffffffu, b, o);
        c += __shfl_down_sync(0xffffffffu, c, o);
    }
    if (lane == 0){ s3[w*3+0] = a; s3[w*3+1] = b; s3[w*3+2] = c; }
    __syncthreads();
    a = b = c = 0.f;
    if (w == 0 && lane < nwarp){ a = s3[lane*3+0]; b = s3[lane*3+1]; c = s3[lane*3+2]; }
    if (w == 0){
        #pragma unroll
        for (int o = 16; o; o >>= 1){
            a += __shfl_down_sync(0xffffffffu, a, o);
            b += __shfl_down_sync(0xffffffffu, b, o);
            c += __shfl_down_sync(0xffffffffu, c, o);
        }
    }
    out[0] = a; out[1] = b; out[2] = c;
    __syncthreads();
}

// ---------------- pass1 (packed, coil-paired): ws(R) = FFT_W( s * p ) ----------------
__global__ void __launch_bounds__(128) k_pass1(){
    int wid = threadIdx.x >> 5, lane = threadIdx.x & 31;
    int wtask = blockIdx.x * 4 + wid;         // [0, B*H*8)
    int cp = wtask & 7;
    int bh = wtask >> 3;
    int b = bh / HH, h = bh % HH;
    int baseA = ((b*CC + 2*cp)*HH + h)*WW;
    int baseB = baseA + HH*WW;
    int pbase = (b*HH + h)*WW;
    u64 m1 = bc2(-1.f);
    C2 v[12];
    #pragma unroll
    for (int j = 0; j < 12; j++){
        int o = 32*j + lane;
        float2 sA = __ldcs(&g_s[baseA + o]);
        float2 sB = __ldcs(&g_s[baseB + o]);
        float2 p  = g_p[pbase + o];
        u64 pre = bc2(p.x), pim = bc2(p.y);
        u64 sre = pk2(sA.x, sB.x), sim = pk2(sA.y, sB.y);
        u64 nsim = mul2(sim, m1);
        v[j].re = fma2(pre, sre, mul2(pim, nsim));
        v[j].im = fma2(pre, sim, mul2(pim, sre));
    }
    fftB2<false>(v, lane, m1);
    #pragma unroll
    for (int m = 0; m < 12; m++){
        float r0, r1, i0, i1;
        unpk2(v[m].re, r0, r1); unpk2(v[m].im, i0, i1);
        g_ws[baseA + 32*m + lane] = make_float2(r0, i0);
        g_ws[baseB + 32*m + lane] = make_float2(r1, i1);
    }
}

// ---------------- pass2 (packed, float4 smem): adjacent column pair per warp ----------
__global__ void __launch_bounds__(128) k_pass2(){
    __shared__ float4 sT[384*5];              // [h][colpair 0..3], stride 5 (conflict-free)
    int tid = threadIdx.x;
    int blk = blockIdx.x;                     // [0, B*C*48)
    int w0 = (blk % 48) * 8;
    int bc = blk / 48; int b = bc / CC;
    int basebc = bc * NPIX;
    const float4* src = (const float4*)(g_ws + basebc);
    for (int idx = tid; idx < 384*4; idx += 128){
        int hr = idx >> 2, c2 = idx & 3;
        sT[hr*5 + c2] = src[hr*(WW/2) + (w0>>1) + c2];
    }
    __syncthreads();
    int wrp = tid >> 5, lane = tid & 31;      // warp owns stored cols w0+2wrp, w0+2wrp+1
    u64 m1 = bc2(-1.f);
    C2 v[12];
    #pragma unroll
    for (int j = 0; j < 12; j++){
        float4 f = sT[(lane + 32*j)*5 + wrp]; // one LDS.128: re0,im0,re1,im1
        v[j].re = pk2(f.x, f.z);
        v[j].im = pk2(f.y, f.w);
    }
    fftA2<false>(v, lane, m1);                // lane holds k-row kb+m
    int mb0 = (b*WW + w0 + 2*wrp) * HH;       // mask rows for the two adjacent columns
    int mb1 = mb0 + HH;
    #pragma unroll
    for (int m = 0; m < 12; m++){
        u64 pm = pk2(g_mask2[mb0 + 32*m + lane], g_mask2[mb1 + 32*m + lane]);
        v[m].re = mul2(v[m].re, pm);
        v[m].im = mul2(v[m].im, pm);
    }
    fftBrev2<true>(v, lane, m1);              // output natural over H
    #pragma unroll
    for (int m = 0; m < 12; m++){
        float r0, r1, i0, i1;
        unpk2(v[m].re, r0, r1); unpk2(v[m].im, i0, i1);
        sT[(lane + 32*m)*5 + wrp] = make_float4(r0, i0, r1, i1);  // one STS.128
    }
    __syncthreads();
    float4* dst = (float4*)(g_ws + basebc);
    for (int idx = tid; idx < 384*4; idx += 128){
        int hr = idx >> 2, c2 = idx & 3;
        dst[hr*(WW/2) + (w0>>1) + c2] = sT[hr*5 + c2];
    }
}

// ---------------- pass3 (packed): Ap + partials; last block per batch computes alpha/beta ----
__global__ void __launch_bounds__(128) k_pass3(const float* __restrict__ lam_p){
    __shared__ float aR[4*384], aI[4*384];
    __shared__ float s3[12];
    __shared__ float sred[8];
    __shared__ int sIsLast;
    int wrp = threadIdx.x >> 5, lane = threadIdx.x & 31;
    int bh = blockIdx.x;                      // [0, B*H)
    int b = bh / HH, h = bh % HH;
    u64 m1 = bc2(-1.f);
    C2 acc[12];
    #pragma unroll
    for (int m = 0; m < 12; m++){ acc[m].re = 0ULL; acc[m].im = 0ULL; }
    int base0 = (b*CC*HH + h)*WW;
    #pragma unroll 1
    for (int k = 0; k < 2; k++){
        int cA = wrp + 8*k, cB = cA + 4;
        int baseA = base0 + cA*HH*WW;
        int baseB = base0 + cB*HH*WW;
        C2 v[12];
        #pragma unroll
        for (int j = 0; j < 12; j++){
            float2 wA = __ldcs(&g_ws[baseA + 32*j + lane]);
            float2 wB = __ldcs(&g_ws[baseB + 32*j + lane]);
            v[j].re = pk2(wA.x, wB.x);
            v[j].im = pk2(wA.y, wB.y);
        }
        fftArev2<true>(v, lane, m1);          // lane holds Xinv[12*lane + m]
        #pragma unroll
        for (int m = 0; m < 12; m++){
            float2 sA = __ldcs(&g_s[baseA + 32*m + lane]);
            float2 sB = __ldcs(&g_s[baseB + 32*m + lane]);
            u64 sre = pk2(sA.x, sB.x), sim = pk2(sA.y, sB.y);
            acc[m].re = fma2(sim, v[m].im, fma2(sre, v[m].re, acc[m].re));
            acc[m].im = fma2(mul2(sim, m1), v[m].re, fma2(sre, v[m].im, acc[m].im));
        }
    }
    #pragma unroll
    for (int m = 0; m < 12; m++){
        float r0, r1, i0, i1;
        unpk2(acc[m].re, r0, r1); unpk2(acc[m].im, i0, i1);
        aR[wrp*384 + 32*m + lane] = r0 + r1;
        aI[wrp*384 + 32*m + lane] = i0 + i1;
    }
    __syncthreads();
    float lam = *lam_p;
    const float sc = 1.0f / (384.0f * 384.0f);
    float pap = 0.f, rap = 0.f, apap = 0.f;
    int t = threadIdx.x;
    #pragma unroll
    for (int q = 0; q < 3; q++){
        int e = t + 128*q;                    // T index
        float ar = aR[e] + aR[384+e] + aR[768+e] + aR[1152+e];
        float ai = aI[e] + aI[384+e] + aI[768+e] + aI[1152+e];
        int idx = bh*WW + e;
        float2 pv = g_p[idx];
        float2 rv = g_r[idx];
        float2 ap = make_float2(fmaf(lam, pv.x, ar*sc), fmaf(lam, pv.y, ai*sc));
        g_Ap[idx] = ap;
        pap  += pv.x*ap.x + pv.y*ap.y;
        rap  += rv.x*ap.x + rv.y*ap.y;
        apap += ap.x*ap.x + ap.y*ap.y;
    }
    float out3[3];
    block_reduce3(pap, rap, apap, s3, 4, out3);
    if (t == 0){
        g_part_pap[bh] = out3[0]; g_part_rap[bh] = out3[1]; g_part_apap[bh] = out3[2];
        __threadfence();
        int old = atomicAdd(&g_cnt[b], 1);
        sIsLast = (old == HH - 1);
    }
    __syncthreads();
    if (sIsLast){
        __threadfence();
        float a1 = 0.f, a2 = 0.f, a3 = 0.f, rr = 0.f;
        #pragma unroll
        for (int q = 0; q < 3; q++){
            int e = b*HH + t + 128*q;
            a1 += g_part_pap[e]; a2 += g_part_rap[e]; a3 += g_part_apap[e];
            rr += g_part_rr[e];
        }
        float tot[3];
        block_reduce3(a1, a2, a3, s3, 4, tot);
        float rtr = block_reduce(rr, sred, 4);
        if (t == 0){
            g_cnt[b] = 0;
            float a = rtr / tot[0];
            float rtrN = fmaf(a*a, tot[2], fmaf(-2.f*a, tot[1], rtr));
            g_scal[2*b] = a; g_scal[2*b+1] = rtrN / rtr;
        }
    }
}

// ---------------- rhs pass 1 (packed): ws(natural) = IFFT_H( y * mask ) ----------------
__global__ void __launch_bounds__(128) k_rhs1(const float* __restrict__ yre,
                                              const float* __restrict__ yim,
                                              const float* __restrict__ mask){
    __shared__ float sR[384*9], sI[384*9];
    int tid = threadIdx.x;
    int blk = blockIdx.x;
    int w0 = (blk % 48) * 8;
    int bc = blk / 48; int b = bc / CC;
    int basebc = bc * NPIX;
    for (int idx = tid; idx < 384*8; idx += 128){
        int h = idx >> 3, cl = idx & 7;
        int g = basebc + h*WW + w0 + cl;
        float mv = mask[(b*HH + h)*WW + w0 + cl];
        sR[h*9+cl] = __ldcs(yre+g)*mv; sI[h*9+cl] = __ldcs(yim+g)*mv;
    }
    __syncthreads();
    int wrp = tid >> 5, lane = tid & 31;      // warp owns cols w0+wrp, w0+wrp+4
    u64 m1 = bc2(-1.f);
    C2 v[12];
    #pragma unroll
    for (int j = 0; j < 12; j++){
        int h = lane + 32*j;
        v[j].re = pk2(sR[h*9+wrp], sR[h*9+wrp+4]);
        v[j].im = pk2(sI[h*9+wrp], sI[h*9+wrp+4]);
    }
    fftA2<true>(v, lane, m1);                 // lane holds rows kb+m
    int kb = 12 * brev5(lane);
    __syncthreads();
    #pragma unroll
    for (int m = 0; m < 12; m++){
        float r0, r1, i0, i1;
        unpk2(v[m].re, r0, r1); unpk2(v[m].im, i0, i1);
        sR[(kb+m)*9+wrp] = r0; sR[(kb+m)*9+wrp+4] = r1;
        sI[(kb+m)*9+wrp] = i0; sI[(kb+m)*9+wrp+4] = i1;
    }
    __syncthreads();
    for (int idx = tid; idx < 384*8; idx += 128){
        int h = idx >> 3, cl = idx & 7;
        g_ws[basebc + h*WW + w0 + cl] = make_float2(sR[h*9+cl], sI[h*9+cl]);
    }
}

// ---------------- rhs pass 2 (packed): writes r,p in T layout; out = 0 ----------
__global__ void __launch_bounds__(128) k_rhs2(const float* __restrict__ xre,
                                              const float* __restrict__ xim,
                                              const float* __restrict__ lam_p,
                                              float2* __restrict__ out){
    __shared__ float aR[4*384], aI[4*384];
    __shared__ float sred[8];
    int wrp = threadIdx.x >> 5, lane = threadIdx.x & 31;
    int bh = blockIdx.x;
    int b = bh / HH, h = bh % HH;
    int kb = 12 * brev5(lane);
    int rb5 = brev5(lane);
    u64 m1 = bc2(-1.f);
    C2 acc[12];
    #pragma unroll
    for (int m = 0; m < 12; m++){ acc[m].re = 0ULL; acc[m].im = 0ULL; }
    int base0 = (b*CC*HH + h)*WW;
    #pragma unroll 1
    for (int k = 0; k < 2; k++){
        int cA = wrp + 8*k, cB = cA + 4;
        int baseA = base0 + cA*HH*WW;
        int baseB = base0 + cB*HH*WW;
        C2 v[12];
        #pragma unroll
        for (int j = 0; j < 12; j++){
            float2 wA = g_ws[baseA + lane + 32*j];
            float2 wB = g_ws[baseB + lane + 32*j];
            v[j].re = pk2(wA.x, wB.x);
            v[j].im = pk2(wA.y, wB.y);
        }
        fftA2<true>(v, lane, m1);             // lane holds natural kb+m
        #pragma unroll
        for (int m = 0; m < 12; m++){
            float2 sA = __ldcs(&g_s[baseA + 32*m + rb5]);
            float2 sB = __ldcs(&g_s[baseB + 32*m + rb5]);
            u64 sre = pk2(sA.x, sB.x), sim = pk2(sA.y, sB.y);
            acc[m].re = fma2(sim, v[m].im, fma2(sre, v[m].re, acc[m].re));
            acc[m].im = fma2(mul2(sim, m1), v[m].re, fma2(sre, v[m].im, acc[m].im));
        }
    }
    #pragma unroll
    for (int m = 0; m < 12; m++){
        float r0, r1, i0, i1;
        unpk2(acc[m].re, r0, r1); unpk2(acc[m].im, i0, i1);
        aR[wrp*384 + kb+m] = r0 + r1;
        aI[wrp*384 + kb+m] = i0 + i1;
    }
    __syncthreads();
    float lam = *lam_p;
    const float sc = 1.0f / 384.0f;   // ortho ifft2 total = unnormalized-inverse / 384
    float rr = 0.f;
    int t = threadIdx.x;
    #pragma unroll
    for (int q = 0; q < 3; q++){
        int e = t + 128*q;                    // natural index
        float ar = aR[e] + aR[384+e] + aR[768+e] + aR[1152+e];
        float ai = aI[e] + aI[384+e] + aI[768+e] + aI[1152+e];
        float2 rhs = make_float2(fmaf(lam, xre[bh*WW+e], ar*sc), fmaf(lam, xim[bh*WW+e], ai*sc));
        int ti = 32*(e%12) + e/12;            // T index
        g_r[bh*WW + ti] = rhs; g_p[bh*WW + ti] = rhs;
        out[bh*WW + e] = make_float2(0.f, 0.f);
        rr += rhs.x*rhs.x + rhs.y*rhs.y;
    }
    float tot = block_reduce(rr, sred, 4);
    if (t == 0) g_part_rr[bh] = tot;
}

// ---------------- slim CG update (T layout): 128 threads x 3 elements ----------------
__global__ void __launch_bounds__(128) k_update(float2* __restrict__ out, int last){
    __shared__ float sred[8];
    int bh = blockIdx.x; int b = bh / HH;
    int t = threadIdx.x;
    float a  = g_scal[2*b];
    float be = g_scal[2*b+1];
    float rr = 0.f;
    if (!last){
        #pragma unroll
        for (int q = 0; q < 3; q++){
            int i = bh*WW + t + 128*q;        // T index
            float2 p = g_p[i], ap = g_Ap[i];
            float2 x = out[i];
            x.x = fmaf(a, p.x, x.x);   x.y = fmaf(a, p.y, x.y);
            out[i] = x;
            float2 r = g_r[i];
            r.x = fmaf(-a, ap.x, r.x); r.y = fmaf(-a, ap.y, r.y);
            g_r[i] = r;
            g_p[i] = make_float2(fmaf(be, p.x, r.x), fmaf(be, p.y, r.y));
            rr += fmaf(r.x, r.x, r.y*r.y);
        }
        float tot = block_reduce(rr, sred, 4);
        if (t == 0) g_part_rr[bh] = tot;      // measured; consumed by next pass3 tail
    } else {
        float2 xs[3];
        #pragma unroll
        for (int q = 0; q < 3; q++){
            int i = bh*WW + t + 128*q;
            float2 p = g_p[i];
            float2 x = out[i];
            xs[q].x = fmaf(a, p.x, x.x); xs[q].y = fmaf(a, p.y, x.y);
        }
        __syncthreads();
        #pragma unroll
        for (int q = 0; q < 3; q++){
            int tt = t + 128*q;
            int n = 12*(tt & 31) + (tt >> 5); // natural index of T slot tt
            out[bh*WW + n] = xs[q];
        }
    }
}

// ---------------- launch ----------------
extern "C" void kernel_launch(void* const* d_in, const int* in_sizes, int n_in,
                              void* d_out, int out_size){
    (void)in_sizes; (void)n_in; (void)out_size;
    const float* lam  = (const float*)d_in[0];
    const float* xre  = (const float*)d_in[1];
    const float* xim  = (const float*)d_in[2];
    const float* yre  = (const float*)d_in[3];
    const float* yim  = (const float*)d_in[4];
    const float* sre  = (const float*)d_in[5];
    const float* sim  = (const float*)d_in[6];
    const float* mask = (const float*)d_in[7];
    float2* out = (float2*)d_out;

    k_init<<<BB*CC*HH, 384>>>(mask, sre, sim);
    k_rhs1<<<BB*CC*48, 128>>>(yre, yim, mask);
    k_rhs2<<<BB*HH, 128>>>(xre, xim, lam, out);

    for (int it = 0; it < 10; it++){
        k_pass1<<<BB*HH*8/4, 128>>>();
        k_pass2<<<BB*CC*48, 128>>>();
        k_pass3<<<BB*HH, 128>>>(lam);
        k_update<<<BB*HH, 128>>>(out, it == 9);
    }
}